// round 8
// baseline (speedup 1.0000x reference)
#include <cuda_runtime.h>

// KVCacheHeadAttention: B=32, E=4096 -> D=128, MAX_TOKENS=2048.
// Prefix-softmax: out[b,s,:] = sum_{t<=s} e_t*v[b,t,:] / sum_{t<=s} e_t.
// R6: TWO kernels.
//  K1 qkv_part: 96 CTAs, split-K partials, no atomics (kernel boundary = sync).
//  K2 fused:    score + chunk totals + decoupled lookback + scan.
//     Publication via st.release.gpu / ld.acquire.gpu (NO __threadfence ->
//     no CCTL.IVALL L1 flush), lane-0-only spin. Per-b done counter resets
//     flags so graph replays start clean.

#define BB 32
#define DD 128
#define D4 32
#define EE 4096
#define MAXT 2048
#define CHUNK 128
#define MAXCH 16
#define NSPLIT 8
#define ECH 128

__device__ float g_part[3][NSPLIT][BB][DD];  // qkv split-K partials
__device__ float g_ctot[BB][MAXCH][DD];      // chunk numerator totals
__device__ float g_dtot[BB][MAXCH];          // chunk denominator totals
__device__ int   g_flag[BB][MAXCH];          // publish flags (zero-init)
__device__ int   g_doneb[BB];                // per-b finished counters

__device__ __forceinline__ float4 f4add(float4 a, float4 b) {
    return make_float4(a.x+b.x, a.y+b.y, a.z+b.z, a.w+b.w);
}
__device__ __forceinline__ float4 f4fma(float s, float4 v, float4 a) {
    return make_float4(fmaf(s,v.x,a.x), fmaf(s,v.y,a.y),
                       fmaf(s,v.z,a.z), fmaf(s,v.w,a.w));
}
__device__ __forceinline__ float4 f4scale(float4 v, float s) {
    return make_float4(v.x*s, v.y*s, v.z*s, v.w*s);
}
__device__ __forceinline__ void st_release_gpu(int* p, int v) {
    asm volatile("st.release.gpu.global.b32 [%0], %1;" :: "l"(p), "r"(v) : "memory");
}
__device__ __forceinline__ int ld_acquire_gpu(const int* p) {
    int v;
    asm volatile("ld.acquire.gpu.global.b32 %0, [%1];" : "=r"(v) : "l"(p) : "memory");
    return v;
}

// ---------------- K1: QKV split-K partials (96 blocks, 512 thr) ----------
// block = (m, dtile, esplit): 32x32 output tile, 512-wide E slice,
// double-buffered smem, partials to g_part (no atomics).
__global__ __launch_bounds__(512) void qkv_part_kernel(
    const float* __restrict__ x,  const float* __restrict__ Wq,
    const float* __restrict__ Wk, const float* __restrict__ Wv) {
    __shared__ float xs[2][32][ECH + 4];
    __shared__ float ws[2][32][ECH + 4];

    int lin = blockIdx.x;
    int m   = lin >> 5;
    int r   = lin & 31;
    int dt  = r >> 3;
    int esp = r & 7;
    const float* W = (m == 0) ? Wq : ((m == 1) ? Wk : Wv);

    int tid = threadIdx.x;
    int ti  = tid & 31;          // batch row
    int tj  = tid >> 5;          // 0..15 -> d pair {tj, tj+16}
    float a0 = 0.f, a1 = 0.f;

    // preload chunk 0
    {
        int e0 = esp * 512;
        for (int i = tid; i < 32 * (ECH / 4); i += 512) {
            int rr = i >> 5;
            int j  = (i & 31) << 2;
            *(float4*)&xs[0][rr][j] = *(const float4*)(x + (size_t)rr * EE + e0 + j);
            *(float4*)&ws[0][rr][j] = *(const float4*)(W + (size_t)(dt * 32 + rr) * EE + e0 + j);
        }
    }
    __syncthreads();

    for (int ch = 0; ch < 4; ch++) {
        int cur = ch & 1, nxt = cur ^ 1;
        if (ch < 3) {
            int e0 = esp * 512 + (ch + 1) * ECH;
            for (int i = tid; i < 32 * (ECH / 4); i += 512) {
                int rr = i >> 5;
                int j  = (i & 31) << 2;
                *(float4*)&xs[nxt][rr][j] = *(const float4*)(x + (size_t)rr * EE + e0 + j);
                *(float4*)&ws[nxt][rr][j] = *(const float4*)(W + (size_t)(dt * 32 + rr) * EE + e0 + j);
            }
        }
        #pragma unroll
        for (int e = 0; e < ECH; e += 4) {
            float4 xa = *(float4*)&xs[cur][ti][e];
            float4 wa = *(float4*)&ws[cur][tj][e];
            float4 wb = *(float4*)&ws[cur][tj + 16][e];
            a0 += xa.x*wa.x + xa.y*wa.y + xa.z*wa.z + xa.w*wa.w;
            a1 += xa.x*wb.x + xa.y*wb.y + xa.z*wb.z + xa.w*wb.w;
        }
        __syncthreads();
    }
    g_part[m][esp][ti][dt * 32 + tj]      = a0;
    g_part[m][esp][ti][dt * 32 + tj + 16] = a1;
}

// -------- K2: fused score + chunk totals + lookback + scan ---------------
__global__ __launch_bounds__(512, 3) void fused_kernel(
    const float* __restrict__ kv, const int* __restrict__ np,
    float* __restrict__ out, int max_k) {

    __shared__ float  qs[DD], kn[DD], es[CHUNK], rden[CHUNK];
    __shared__ float4 vns4[D4];
    __shared__ float4 part[16][D4];
    __shared__ float  pden[16];
    __shared__ float  warp_sums[4];
    __shared__ int    last;

    int tid = threadIdx.x;
    int b   = blockIdx.y, c = blockIdx.x;

    // prologue: reduce split-K partials (96 threads, float4)
    if (tid < 96) {
        int m  = tid >> 5;
        int dd = tid & 31;
        float4 acc = make_float4(0.f, 0.f, 0.f, 0.f);
        #pragma unroll
        for (int e = 0; e < NSPLIT; e++)
            acc = f4add(acc, *((const float4*)&g_part[m][e][b][0] + dd));
        if (m == 0)      *((float4*)qs + dd) = acc;
        else if (m == 1) *((float4*)kn + dd) = acc;
        else             vns4[dd] = acc;
    }
    __syncthreads();

    int npos = np[b];
    int t0   = c * CHUNK;

    // phase C: scores (4 lanes per token, quarter-dot + shfl)
    {
        int tok = tid >> 2, qq = tid & 3;
        int t   = t0 + tok;
        const float* krow = (t == npos) ? kn
                          : kv + ((size_t)b * MAXT + t) * DD;
        float sdot = 0.0f;
        int d0 = qq * 32;
        #pragma unroll
        for (int d = 0; d < 32; d += 4) {
            float4 kk = *(const float4*)(krow + d0 + d);
            sdot += qs[d0+d]*kk.x + qs[d0+d+1]*kk.y
                  + qs[d0+d+2]*kk.z + qs[d0+d+3]*kk.w;
        }
        sdot += __shfl_xor_sync(0xffffffffu, sdot, 1);
        sdot += __shfl_xor_sync(0xffffffffu, sdot, 2);
        float e = (t < max_k) ? expf(sdot * 0.08838834764831845f) : 0.0f;
        if (qq == 0) es[tok] = e;
    }
    __syncthreads();

    // phase D: 8-token numerator partials + den warp-scan
    int s  = tid >> 5;       // warp = 8-token sub-chunk
    int d4 = tid & 31;
    int tb = t0 + s * 8;
    const float4* vbase = (const float4*)(kv + (size_t)BB * MAXT * DD
                                          + ((size_t)b * MAXT + tb) * DD) + d4;
    {
        float4 psum = make_float4(0.f, 0.f, 0.f, 0.f);
        #pragma unroll
        for (int uu = 0; uu < 8; uu++) {
            float4 xv = vbase[(size_t)uu * D4];
            if (tb + uu == npos) xv = vns4[d4];
            psum = f4fma(es[s * 8 + uu], xv, psum);
        }
        part[s][d4] = psum;
    }
    float dv = 0.0f;
    if (tid < 128) {
        dv = es[tid];
        int lane = tid & 31;
        #pragma unroll
        for (int o = 1; o < 32; o <<= 1) {
            float n = __shfl_up_sync(0xffffffffu, dv, o);
            if (lane >= o) dv += n;
        }
        if (lane == 31) warp_sums[tid >> 5] = dv;
    }
    __syncthreads();

    // own exclusive prefix (registers) + publish chunk totals
    float4 pref = make_float4(0.f, 0.f, 0.f, 0.f);
    for (int j = 0; j < s; j++) pref = f4add(pref, part[j][d4]);
    if (s == 15)
        *((float4*)&g_ctot[b][c][0] + d4) = f4add(pref, part[15][d4]);
    if (tid == 0)
        g_dtot[b][c] = warp_sums[0] + warp_sums[1] + warp_sums[2] + warp_sums[3];
    __syncthreads();
    if (tid == 0) st_release_gpu(&g_flag[b][c], 1);

    // phase E: lookback — warp i fetches predecessor i (lane-0 spin)
    if (s < c) {
        if (d4 == 0) {
            while (ld_acquire_gpu(&g_flag[b][s]) == 0) { __nanosleep(64); }
        }
        __syncwarp();
        part[s][d4] = *((const float4*)&g_ctot[b][s][0] + d4);
        if (d4 == 0) pden[s] = g_dtot[b][s];
    } else {
        part[s][d4] = make_float4(0.f, 0.f, 0.f, 0.f);
        if (d4 == 0) pden[s] = 0.0f;
    }
    __syncthreads();

    // bases + reciprocal denominators
    float4 bnum = make_float4(0.f, 0.f, 0.f, 0.f);
    float  bden = 0.0f;
    for (int i = 0; i < c; i++) {
        bnum = f4add(bnum, part[i][d4]);
        bden += pden[i];
    }
    if (tid < 128) {
        int w = tid >> 5;
        float wb = bden;
        for (int i = 0; i < w; i++) wb += warp_sums[i];
        rden[tid] = 1.0f / (wb + dv);
    }
    __syncthreads();

    // phase F: final scan (V reload is L1/L2-hot), scaled stores
    float4 acc = f4add(bnum, pref);
    float4* obase = (float4*)(out + ((size_t)b * max_k + tb) * DD) + d4;
    #pragma unroll
    for (int uu = 0; uu < 8; uu++) {
        float4 xv = vbase[(size_t)uu * D4];
        if (tb + uu == npos) xv = vns4[d4];
        acc = f4fma(es[s * 8 + uu], xv, acc);
        if (tb + uu < max_k)
            obase[(size_t)uu * D4] = f4scale(acc, rden[s * 8 + uu]);
    }

    // phase G: per-b self-clean for graph replay
    __syncthreads();                         // all flag reads & outputs done
    if (tid == 0)
        last = (atomicAdd(&g_doneb[b], 1) == (int)gridDim.x - 1);
    __syncthreads();
    if (last) {
        if (tid < MAXCH) g_flag[b][tid] = 0;
        if (tid == 0)    g_doneb[b] = 0;
    }
}

// ----------------------------------------------------------------- launch
extern "C" void kernel_launch(void* const* d_in, const int* in_sizes, int n_in,
                              void* d_out, int out_size) {
    const float* x   = (const float*)d_in[0];
    const float* Wq  = (const float*)d_in[1];
    const float* Wk  = (const float*)d_in[2];
    const float* Wv  = (const float*)d_in[3];
    const float* kvc = (const float*)d_in[4];
    const int*   np  = (const int*)d_in[5];
    float* out = (float*)d_out;

    int max_k   = out_size / (BB * DD);
    int nchunks = (max_k + CHUNK - 1) / CHUNK;   // 12 for max_k=1536

    qkv_part_kernel<<<96, 512>>>(x, Wq, Wk, Wv);
    fused_kernel<<<dim3(nchunks, BB), 512>>>(kvc, np, out, max_k);
}

// round 9
// speedup vs baseline: 1.1828x; 1.1828x over previous
#include <cuda_runtime.h>

// KVCacheHeadAttention: B=32, E=4096 -> D=128, MAX_TOKENS=2048.
// Prefix-softmax: out[b,s,:] = sum_{t<=s} e_t*v[b,t,:] / sum_{t<=s} e_t.
// R8: 3 kernels, NO cross-CTA spinning (every lookback/spin variant lost to
// kernel boundaries on this chip).
//  K1 qkv_part: 96 CTAs, atomic-free split-K partials (no zero kernel).
//  K2 score:    partial-reduce prologue + scores (streaming K loads) +
//               32-token chunk num/den partials.
//  K3 scan:     parallel base reduction + intra-chunk scan, streaming stores
//               (__stcs) so the 25MB output never evicts L2-hot V.

#define BB 32
#define DD 128
#define D4 32
#define EE 4096
#define MAXT 2048
#define CHUNK 128
#define SUB 32
#define MAXSUB 64
#define NSPLIT 8
#define ECH 128

__device__ float g_part[3][NSPLIT][BB][DD];  // qkv split-K partials
__device__ float g_e[BB][MAXT];              // exp(scores)
__device__ float g_cnum[BB][MAXSUB][DD];     // 32-token numerator partials
__device__ float g_cden[BB][MAXSUB];         // 32-token denominator partials

__device__ __forceinline__ float4 f4add(float4 a, float4 b) {
    return make_float4(a.x+b.x, a.y+b.y, a.z+b.z, a.w+b.w);
}
__device__ __forceinline__ float4 f4fma(float s, float4 v, float4 a) {
    return make_float4(fmaf(s,v.x,a.x), fmaf(s,v.y,a.y),
                       fmaf(s,v.z,a.z), fmaf(s,v.w,a.w));
}
__device__ __forceinline__ float4 f4scale(float4 v, float s) {
    return make_float4(v.x*s, v.y*s, v.z*s, v.w*s);
}

// ---------------- K1: QKV split-K partials (96 blocks, 512 thr) ----------
__global__ __launch_bounds__(512) void qkv_part_kernel(
    const float* __restrict__ x,  const float* __restrict__ Wq,
    const float* __restrict__ Wk, const float* __restrict__ Wv) {
    __shared__ float xs[2][32][ECH + 4];
    __shared__ float ws[2][32][ECH + 4];

    int lin = blockIdx.x;
    int m   = lin >> 5;
    int r   = lin & 31;
    int dt  = r >> 3;
    int esp = r & 7;
    const float* W = (m == 0) ? Wq : ((m == 1) ? Wk : Wv);

    int tid = threadIdx.x;
    int ti  = tid & 31;
    int tj  = tid >> 5;
    float a0 = 0.f, a1 = 0.f;

    {
        int e0 = esp * 512;
        for (int i = tid; i < 32 * (ECH / 4); i += 512) {
            int rr = i >> 5;
            int j  = (i & 31) << 2;
            *(float4*)&xs[0][rr][j] = *(const float4*)(x + (size_t)rr * EE + e0 + j);
            *(float4*)&ws[0][rr][j] = __ldcs((const float4*)(W + (size_t)(dt * 32 + rr) * EE + e0 + j));
        }
    }
    __syncthreads();

    for (int ch = 0; ch < 4; ch++) {
        int cur = ch & 1, nxt = cur ^ 1;
        if (ch < 3) {
            int e0 = esp * 512 + (ch + 1) * ECH;
            for (int i = tid; i < 32 * (ECH / 4); i += 512) {
                int rr = i >> 5;
                int j  = (i & 31) << 2;
                *(float4*)&xs[nxt][rr][j] = *(const float4*)(x + (size_t)rr * EE + e0 + j);
                *(float4*)&ws[nxt][rr][j] = __ldcs((const float4*)(W + (size_t)(dt * 32 + rr) * EE + e0 + j));
            }
        }
        #pragma unroll
        for (int e = 0; e < ECH; e += 4) {
            float4 xa = *(float4*)&xs[cur][ti][e];
            float4 wa = *(float4*)&ws[cur][tj][e];
            float4 wb = *(float4*)&ws[cur][tj + 16][e];
            a0 += xa.x*wa.x + xa.y*wa.y + xa.z*wa.z + xa.w*wa.w;
            a1 += xa.x*wb.x + xa.y*wb.y + xa.z*wb.z + xa.w*wb.w;
        }
        __syncthreads();
    }
    g_part[m][esp][ti][dt * 32 + tj]      = a0;
    g_part[m][esp][ti][dt * 32 + tj + 16] = a1;
}

// -------- K2: score + 32-token chunk partials (grid nchunks x B) ---------
__global__ __launch_bounds__(512) void score_kernel(
    const float* __restrict__ kv, const int* __restrict__ np, int max_k) {
    int b = blockIdx.y, c = blockIdx.x, tid = threadIdx.x;
    __shared__ float qs[DD], kn[DD], es[CHUNK];
    __shared__ float4 vns4[D4];
    __shared__ float4 red[4][4][D4];

    // prologue: reduce split-K partials (96 threads, float4 over 8 splits)
    if (tid < 96) {
        int m  = tid >> 5;
        int dd = tid & 31;
        float4 acc = make_float4(0.f, 0.f, 0.f, 0.f);
        #pragma unroll
        for (int e = 0; e < NSPLIT; e++)
            acc = f4add(acc, *((const float4*)&g_part[m][e][b][0] + dd));
        if (m == 0)      *((float4*)qs + dd) = acc;
        else if (m == 1) *((float4*)kn + dd) = acc;
        else             vns4[dd] = acc;
    }
    __syncthreads();

    int npos = np[b];
    int t0   = c * CHUNK;

    // scores: 4 lanes per token, streaming K loads (K read exactly once)
    {
        int tok = tid >> 2, qq = tid & 3;
        int t   = t0 + tok;
        float sdot = 0.0f;
        int d0 = qq * 32;
        if (t == npos) {
            #pragma unroll
            for (int d = 0; d < 32; d++) sdot += qs[d0 + d] * kn[d0 + d];
        } else {
            const float4* krow = (const float4*)(kv + ((size_t)b * MAXT + t) * DD) + qq * 8;
            #pragma unroll
            for (int d = 0; d < 8; d++) {
                float4 kk = __ldcs(krow + d);
                sdot += qs[d0+4*d]*kk.x + qs[d0+4*d+1]*kk.y
                      + qs[d0+4*d+2]*kk.z + qs[d0+4*d+3]*kk.w;
            }
        }
        sdot += __shfl_xor_sync(0xffffffffu, sdot, 1);
        sdot += __shfl_xor_sync(0xffffffffu, sdot, 2);
        float e = (t < max_k) ? expf(sdot * 0.08838834764831845f) : 0.0f;
        if (qq == 0) {
            es[tok]   = e;
            g_e[b][t] = e;
        }
    }
    __syncthreads();

    // 32-token denominators (warps 0..3)
    if (tid < 128) {
        float de = es[tid];
        #pragma unroll
        for (int o = 16; o; o >>= 1) de += __shfl_xor_sync(0xffffffffu, de, o);
        if ((tid & 31) == 0) g_cden[b][c * 4 + (tid >> 5)] = de;
    }

    // numerator partials: thread = (sc, tq, d4), 8 LDG.128 each
    int sc = tid >> 7;
    int tq = (tid >> 5) & 3;
    int d4 = tid & 31;
    int tb = t0 + sc * SUB + tq * 8;
    const float4* vbase = (const float4*)(kv + (size_t)BB * MAXT * DD
                                          + ((size_t)b * MAXT + tb) * DD) + d4;
    float4 acc = make_float4(0.f, 0.f, 0.f, 0.f);
    #pragma unroll
    for (int u = 0; u < 8; u++) {
        float4 vv = vbase[(size_t)u * D4];
        if (tb + u == npos) vv = vns4[d4];
        acc = f4fma(es[sc * SUB + tq * 8 + u], vv, acc);
    }
    red[sc][tq][d4] = acc;
    __syncthreads();
    if (tid < 128) {
        int sc2 = tid >> 5, dd = tid & 31;
        float4 s0 = f4add(f4add(red[sc2][0][dd], red[sc2][1][dd]),
                          f4add(red[sc2][2][dd], red[sc2][3][dd]));
        *((float4*)&g_cnum[b][c * 4 + sc2][0] + dd) = s0;
    }
}

// --------- K3: prefix scan + output (grid nchunks x B, 512 thr) ----------
__global__ __launch_bounds__(512) void scan_kernel(
    const float* __restrict__ kv, const int* __restrict__ np,
    float* __restrict__ out, int max_k) {
    int b = blockIdx.y, c = blockIdx.x, tid = threadIdx.x;
    __shared__ float es[CHUNK], rden[CHUNK];
    __shared__ float4 vns4[D4];
    __shared__ float4 bred[16][D4];
    __shared__ float4 part[16][D4];
    __shared__ float warp_sums[4];
    __shared__ float denbase_s;

    int t0 = c * CHUNK;
    if (tid < CHUNK) es[tid] = g_e[b][t0 + tid];
    if (tid >= 480) {                       // warp 15: reduce v-new partials
        int dd = tid - 480;
        float4 acc = make_float4(0.f, 0.f, 0.f, 0.f);
        #pragma unroll
        for (int e = 0; e < NSPLIT; e++)
            acc = f4add(acc, *((const float4*)&g_part[2][e][b][0] + dd));
        vns4[dd] = acc;
    }

    int s  = tid >> 5;       // 0..15
    int d4 = tid & 31;

    // chunk numerator base: rows i < 4c, 16-slice stride + tree
    {
        float4 acc = make_float4(0.f, 0.f, 0.f, 0.f);
        int nrow = 4 * c;
        for (int i = s; i < nrow; i += 16)
            acc = f4add(acc, *((const float4*)&g_cnum[b][i][0] + d4));
        bred[s][d4] = acc;
    }
    // denominator base: warp 0
    if (tid < 32) {
        float db = 0.0f;
        int nrow = 4 * c;
        for (int i = tid; i < nrow; i += 32) db += g_cden[b][i];
        #pragma unroll
        for (int o = 16; o; o >>= 1) db += __shfl_xor_sync(0xffffffffu, db, o);
        if (tid == 0) denbase_s = db;
    }
    __syncthreads();
    #pragma unroll
    for (int off = 8; off; off >>= 1) {
        if (s < off) bred[s][d4] = f4add(bred[s][d4], bred[s + off][d4]);
        __syncthreads();
    }

    // denominator prefixes over 128 tokens
    float dv = 0.0f;
    if (tid < 128) {
        dv = es[tid];
        int lane = tid & 31;
        #pragma unroll
        for (int o = 1; o < 32; o <<= 1) {
            float n = __shfl_up_sync(0xffffffffu, dv, o);
            if (lane >= o) dv += n;
        }
        if (lane == 31) warp_sums[tid >> 5] = dv;
    }
    __syncthreads();
    if (tid < 128) {
        int w = tid >> 5;
        float wb = denbase_s;
        for (int i = 0; i < w; i++) wb += warp_sums[i];
        rden[tid] = 1.0f / (wb + dv);
    }

    // V into registers + 8-token partial
    int npos = np[b];
    int tb   = t0 + s * 8;
    const float4* vbase = (const float4*)(kv + (size_t)BB * MAXT * DD
                                          + ((size_t)b * MAXT + tb) * DD) + d4;
    float4 vv[8];
    float4 psum = make_float4(0.f, 0.f, 0.f, 0.f);
    #pragma unroll
    for (int u = 0; u < 8; u++) {
        float4 x = vbase[(size_t)u * D4];
        if (tb + u == npos) x = vns4[d4];
        vv[u] = x;
        psum = f4fma(es[s * 8 + u], x, psum);
    }
    part[s][d4] = psum;
    __syncthreads();

    float4 acc = bred[0][d4];
    for (int j = 0; j < s; j++) acc = f4add(acc, part[j][d4]);

    // scan + streaming stores (output written exactly once, never re-read)
    float4* obase = (float4*)(out + ((size_t)b * max_k + tb) * DD) + d4;
    #pragma unroll
    for (int u = 0; u < 8; u++) {
        acc = f4fma(es[s * 8 + u], vv[u], acc);
        if (tb + u < max_k)
            __stcs(obase + (size_t)u * D4, f4scale(acc, rden[s * 8 + u]));
    }
}

// ----------------------------------------------------------------- launch
extern "C" void kernel_launch(void* const* d_in, const int* in_sizes, int n_in,
                              void* d_out, int out_size) {
    const float* x   = (const float*)d_in[0];
    const float* Wq  = (const float*)d_in[1];
    const float* Wk  = (const float*)d_in[2];
    const float* Wv  = (const float*)d_in[3];
    const float* kvc = (const float*)d_in[4];
    const int*   np  = (const int*)d_in[5];
    float* out = (float*)d_out;

    int max_k   = out_size / (BB * DD);
    int nchunks = (max_k + CHUNK - 1) / CHUNK;   // 12 for max_k=1536

    qkv_part_kernel<<<96, 512>>>(x, Wq, Wk, Wv);
    score_kernel<<<dim3(nchunks, BB), 512>>>(kvc, np, max_k);
    scan_kernel<<<dim3(nchunks, BB), 512>>>(kvc, np, out, max_k);
}

// round 10
// speedup vs baseline: 1.2541x; 1.0603x over previous
#include <cuda_runtime.h>

// KVCacheHeadAttention: B=32, E=4096 -> D=128, MAX_TOKENS=2048.
// Prefix-softmax: out[b,s,:] = sum_{t<=s} e_t*v[b,t,:] / sum_{t<=s} e_t.
// R9: 3 kernels, no cross-CTA sync.
//  K1 qkv_part: 384 CTAs (3m x 4dt x 32 esplits), 256 thr, atomic-free
//     split-K partials -> g_part (R2 geometry + R8 publication; fixes the
//     17.4us latency-bound 96-CTA version).
//  K2 score: split reduce prologue + scores + 32-token chunk partials.
//  K3 scan:  parallel base reduce + intra-chunk scan, streaming stores.

#define BB 32
#define DD 128
#define D4 32
#define EE 4096
#define MAXT 2048
#define CHUNK 128
#define SUB 32
#define MAXSUB 64
#define NSPLIT 32
#define ECH 128

__device__ float g_part[3][NSPLIT][BB][DD];  // qkv split-K partials
__device__ float g_e[BB][MAXT];              // exp(scores)
__device__ float g_cnum[BB][MAXSUB][DD];     // 32-token numerator partials
__device__ float g_cden[BB][MAXSUB];         // 32-token denominator partials

__device__ __forceinline__ float4 f4add(float4 a, float4 b) {
    return make_float4(a.x+b.x, a.y+b.y, a.z+b.z, a.w+b.w);
}
__device__ __forceinline__ float4 f4fma(float s, float4 v, float4 a) {
    return make_float4(fmaf(s,v.x,a.x), fmaf(s,v.y,a.y),
                       fmaf(s,v.z,a.z), fmaf(s,v.w,a.w));
}
__device__ __forceinline__ float4 f4scale(float4 v, float s) {
    return make_float4(v.x*s, v.y*s, v.z*s, v.w*s);
}

// ------------- K1: QKV split-K partials (384 blocks, 256 thr) ------------
// blockIdx.x = m*4 + dtile (12), blockIdx.y = esplit (32). One 128-wide
// E chunk per block, 2x2 outputs per thread, no atomics.
__global__ __launch_bounds__(256) void qkv_part_kernel(
    const float* __restrict__ x,  const float* __restrict__ Wq,
    const float* __restrict__ Wk, const float* __restrict__ Wv) {
    __shared__ float xs[32][ECH + 4];
    __shared__ float ws[32][ECH + 4];
    int m   = blockIdx.x >> 2;
    int dt  = blockIdx.x & 3;
    int esp = blockIdx.y;
    const float* W = (m == 0) ? Wq : ((m == 1) ? Wk : Wv);
    int e0  = esp * ECH;
    int tid = threadIdx.x;

    for (int i = tid; i < 32 * (ECH / 4); i += 256) {
        int r = i >> 5;
        int j = (i & 31) << 2;
        *(float4*)&xs[r][j] = *(const float4*)(x + (size_t)r * EE + e0 + j);
        *(float4*)&ws[r][j] = __ldcs((const float4*)(W + (size_t)(dt * 32 + r) * EE + e0 + j));
    }
    __syncthreads();

    int ti = tid & 15, tj = tid >> 4;  // b-pair {ti,ti+16}, d-pair {tj,tj+16}
    float a00 = 0.f, a01 = 0.f, a10 = 0.f, a11 = 0.f;
    #pragma unroll
    for (int e = 0; e < ECH; e += 4) {
        float4 xa = *(float4*)&xs[ti][e];
        float4 xb = *(float4*)&xs[ti + 16][e];
        float4 wa = *(float4*)&ws[tj][e];
        float4 wb = *(float4*)&ws[tj + 16][e];
        a00 += xa.x*wa.x + xa.y*wa.y + xa.z*wa.z + xa.w*wa.w;
        a01 += xa.x*wb.x + xa.y*wb.y + xa.z*wb.z + xa.w*wb.w;
        a10 += xb.x*wa.x + xb.y*wa.y + xb.z*wa.z + xb.w*wa.w;
        a11 += xb.x*wb.x + xb.y*wb.y + xb.z*wb.z + xb.w*wb.w;
    }
    g_part[m][esp][ti][dt * 32 + tj]           = a00;
    g_part[m][esp][ti][dt * 32 + tj + 16]      = a01;
    g_part[m][esp][ti + 16][dt * 32 + tj]      = a10;
    g_part[m][esp][ti + 16][dt * 32 + tj + 16] = a11;
}

// -------- K2: score + 32-token chunk partials (grid nchunks x B) ---------
__global__ __launch_bounds__(512) void score_kernel(
    const float* __restrict__ kv, const int* __restrict__ np, int max_k) {
    int b = blockIdx.y, c = blockIdx.x, tid = threadIdx.x;
    __shared__ float qs[DD], kn[DD], es[CHUNK];
    __shared__ float4 vns4[D4];
    __shared__ float4 red[4][4][D4];

    // prologue: reduce split-K partials (96 threads, float4 over 32 splits)
    if (tid < 96) {
        int m  = tid >> 5;
        int dd = tid & 31;
        float4 acc = make_float4(0.f, 0.f, 0.f, 0.f);
        #pragma unroll
        for (int e = 0; e < NSPLIT; e++)
            acc = f4add(acc, *((const float4*)&g_part[m][e][b][0] + dd));
        if (m == 0)      *((float4*)qs + dd) = acc;
        else if (m == 1) *((float4*)kn + dd) = acc;
        else             vns4[dd] = acc;
    }
    __syncthreads();

    int npos = np[b];
    int t0   = c * CHUNK;

    // scores: 4 lanes per token, streaming K loads
    {
        int tok = tid >> 2, qq = tid & 3;
        int t   = t0 + tok;
        float sdot = 0.0f;
        int d0 = qq * 32;
        if (t == npos) {
            #pragma unroll
            for (int d = 0; d < 32; d++) sdot += qs[d0 + d] * kn[d0 + d];
        } else {
            const float4* krow = (const float4*)(kv + ((size_t)b * MAXT + t) * DD) + qq * 8;
            #pragma unroll
            for (int d = 0; d < 8; d++) {
                float4 kk = __ldcs(krow + d);
                sdot += qs[d0+4*d]*kk.x + qs[d0+4*d+1]*kk.y
                      + qs[d0+4*d+2]*kk.z + qs[d0+4*d+3]*kk.w;
            }
        }
        sdot += __shfl_xor_sync(0xffffffffu, sdot, 1);
        sdot += __shfl_xor_sync(0xffffffffu, sdot, 2);
        float e = (t < max_k) ? expf(sdot * 0.08838834764831845f) : 0.0f;
        if (qq == 0) {
            es[tok]   = e;
            g_e[b][t] = e;
        }
    }
    __syncthreads();

    // 32-token denominators (warps 0..3)
    if (tid < 128) {
        float de = es[tid];
        #pragma unroll
        for (int o = 16; o; o >>= 1) de += __shfl_xor_sync(0xffffffffu, de, o);
        if ((tid & 31) == 0) g_cden[b][c * 4 + (tid >> 5)] = de;
    }

    // numerator partials: thread = (sc, tq, d4), 8 LDG.128 each
    int sc = tid >> 7;
    int tq = (tid >> 5) & 3;
    int d4 = tid & 31;
    int tb = t0 + sc * SUB + tq * 8;
    const float4* vbase = (const float4*)(kv + (size_t)BB * MAXT * DD
                                          + ((size_t)b * MAXT + tb) * DD) + d4;
    float4 acc = make_float4(0.f, 0.f, 0.f, 0.f);
    #pragma unroll
    for (int u = 0; u < 8; u++) {
        float4 vv = vbase[(size_t)u * D4];
        if (tb + u == npos) vv = vns4[d4];
        acc = f4fma(es[sc * SUB + tq * 8 + u], vv, acc);
    }
    red[sc][tq][d4] = acc;
    __syncthreads();
    if (tid < 128) {
        int sc2 = tid >> 5, dd = tid & 31;
        float4 s0 = f4add(f4add(red[sc2][0][dd], red[sc2][1][dd]),
                          f4add(red[sc2][2][dd], red[sc2][3][dd]));
        *((float4*)&g_cnum[b][c * 4 + sc2][0] + dd) = s0;
    }
}

// --------- K3: prefix scan + output (grid nchunks x B, 512 thr) ----------
__global__ __launch_bounds__(512) void scan_kernel(
    const float* __restrict__ kv, const int* __restrict__ np,
    float* __restrict__ out, int max_k) {
    int b = blockIdx.y, c = blockIdx.x, tid = threadIdx.x;
    __shared__ float es[CHUNK], rden[CHUNK];
    __shared__ float4 vns4[D4];
    __shared__ float4 bred[16][D4];
    __shared__ float4 part[16][D4];
    __shared__ float warp_sums[4];
    __shared__ float denbase_s;

    int t0 = c * CHUNK;
    if (tid < CHUNK) es[tid] = g_e[b][t0 + tid];
    if (tid >= 480) {                       // warp 15: reduce v-new partials
        int dd = tid - 480;
        float4 acc = make_float4(0.f, 0.f, 0.f, 0.f);
        #pragma unroll
        for (int e = 0; e < NSPLIT; e++)
            acc = f4add(acc, *((const float4*)&g_part[2][e][b][0] + dd));
        vns4[dd] = acc;
    }

    int s  = tid >> 5;       // 0..15
    int d4 = tid & 31;

    // chunk numerator base: rows i < 4c, 16-slice stride + tree
    {
        float4 acc = make_float4(0.f, 0.f, 0.f, 0.f);
        int nrow = 4 * c;
        for (int i = s; i < nrow; i += 16)
            acc = f4add(acc, *((const float4*)&g_cnum[b][i][0] + d4));
        bred[s][d4] = acc;
    }
    // denominator base: warp 0
    if (tid < 32) {
        float db = 0.0f;
        int nrow = 4 * c;
        for (int i = tid; i < nrow; i += 32) db += g_cden[b][i];
        #pragma unroll
        for (int o = 16; o; o >>= 1) db += __shfl_xor_sync(0xffffffffu, db, o);
        if (tid == 0) denbase_s = db;
    }
    __syncthreads();
    #pragma unroll
    for (int off = 8; off; off >>= 1) {
        if (s < off) bred[s][d4] = f4add(bred[s][d4], bred[s + off][d4]);
        __syncthreads();
    }

    // denominator prefixes over 128 tokens
    float dv = 0.0f;
    if (tid < 128) {
        dv = es[tid];
        int lane = tid & 31;
        #pragma unroll
        for (int o = 1; o < 32; o <<= 1) {
            float n = __shfl_up_sync(0xffffffffu, dv, o);
            if (lane >= o) dv += n;
        }
        if (lane == 31) warp_sums[tid >> 5] = dv;
    }
    __syncthreads();
    if (tid < 128) {
        int w = tid >> 5;
        float wb = denbase_s;
        for (int i = 0; i < w; i++) wb += warp_sums[i];
        rden[tid] = 1.0f / (wb + dv);
    }

    // V into registers + 8-token partial
    int npos = np[b];
    int tb   = t0 + s * 8;
    const float4* vbase = (const float4*)(kv + (size_t)BB * MAXT * DD
                                          + ((size_t)b * MAXT + tb) * DD) + d4;
    float4 vv[8];
    float4 psum = make_float4(0.f, 0.f, 0.f, 0.f);
    #pragma unroll
    for (int u = 0; u < 8; u++) {
        float4 x = vbase[(size_t)u * D4];
        if (tb + u == npos) x = vns4[d4];
        vv[u] = x;
        psum = f4fma(es[s * 8 + u], x, psum);
    }
    part[s][d4] = psum;
    __syncthreads();

    float4 acc = bred[0][d4];
    for (int j = 0; j < s; j++) acc = f4add(acc, part[j][d4]);

    // scan + streaming stores
    float4* obase = (float4*)(out + ((size_t)b * max_k + tb) * DD) + d4;
    #pragma unroll
    for (int u = 0; u < 8; u++) {
        acc = f4fma(es[s * 8 + u], vv[u], acc);
        if (tb + u < max_k)
            __stcs(obase + (size_t)u * D4, f4scale(acc, rden[s * 8 + u]));
    }
}

// ----------------------------------------------------------------- launch
extern "C" void kernel_launch(void* const* d_in, const int* in_sizes, int n_in,
                              void* d_out, int out_size) {
    const float* x   = (const float*)d_in[0];
    const float* Wq  = (const float*)d_in[1];
    const float* Wk  = (const float*)d_in[2];
    const float* Wv  = (const float*)d_in[3];
    const float* kvc = (const float*)d_in[4];
    const int*   np  = (const int*)d_in[5];
    float* out = (float*)d_out;

    int max_k   = out_size / (BB * DD);
    int nchunks = (max_k + CHUNK - 1) / CHUNK;   // 12 for max_k=1536

    qkv_part_kernel<<<dim3(12, NSPLIT), 256>>>(x, Wq, Wk, Wv);
    score_kernel<<<dim3(nchunks, BB), 512>>>(kvc, np, max_k);
    scan_kernel<<<dim3(nchunks, BB), 512>>>(kvc, np, out, max_k);
}